// round 16
// baseline (speedup 1.0000x reference)
#include <cuda_runtime.h>
#include <cuda_fp16.h>
#include <math.h>
#include <stdint.h>

#define Bsz  32
#define Tseq 512
#define Dm   512
#define Lnum 4
#define Hn   8
#define HDim 64
#define Ff   2048
#define Kcb  8192
#define Mrows (Bsz*Tseq)   // 16384
#define DD (Dm*Dm)

// GEMM tiling: 128x256 tile, BK=64, 2-plane fp16 split, TMEM 256 cols
#define BM 128
#define BN 256
#define TILE_B 16384                       // one 128x64 fp16 tile, SW128 (128B rows)
#define STAGE_BYTES (6*TILE_B)             // A0,A1 (2) + B0,B1 (4 sub-tiles) = 98304
#define SMEM_DYN (2048 + 2*STAGE_BYTES)    // 198656
// idesc kind::f16: F32 acc(1<<4), FP16 a/b, N=64 (8<<17), M=128 (8<<24)
#define IDESC_FP16 ((1u<<4)|(8u<<17)|(8u<<24))
#define DESC_BASE 0x4000404000010000ull    // SW128, version=1, SBO=64, LBO=1
// attention smem: Q^T[64][132] + K^T[64][132] + V[128][68] + P[128][132]
#define ATT_SMEM ((2*64*132 + 128*68 + 128*132)*4)   // 169984

#if defined(__CUDA_ARCH__) && (defined(__CUDA_ARCH_FEAT_SM103_ALL) || defined(__CUDA_ARCH_FEAT_SM100_ALL) || defined(__CUDA_ARCH_FEAT_SM101_ALL))
#define HAS_TCGEN05 1
#else
#define HAS_TCGEN05 0
#endif

typedef __half f16;

// ---------------- scratch globals -------------------------------------------
__device__ float g_x[Mrows*Dm];
__device__ __align__(256) f16 g_x0[Mrows*Dm], g_x1[Mrows*Dm];
__device__ float g_q[Mrows*Dm];
__device__ float g_k[Mrows*Dm];
__device__ float g_v[Mrows*Dm];
__device__ __align__(256) f16 g_a0[Mrows*Dm], g_a1[Mrows*Dm];
__device__ float g_o[Mrows*Dm];
__device__ __align__(256) f16 g_h0[(size_t)Mrows*Ff], g_h1[(size_t)Mrows*Ff];
__device__ float g_cos[Tseq*32];
__device__ float g_sin[Tseq*32];
__device__ float g_cnorm[Kcb];
__device__ int   g_idx[Mrows];
__device__ float g_lpart[Mrows];
__device__ float g_pb[Mrows*32];
__device__ int   g_pi[Mrows*32];
// split weights (transposed to [N][K]) and codebook, 2 fp16 planes each
__device__ __align__(256) f16 g_wq0[Lnum*DD], g_wq1[Lnum*DD];
__device__ __align__(256) f16 g_wk0[Lnum*DD], g_wk1[Lnum*DD];
__device__ __align__(256) f16 g_wv0[Lnum*DD], g_wv1[Lnum*DD];
__device__ __align__(256) f16 g_wo0[Lnum*DD], g_wo1[Lnum*DD];
__device__ __align__(256) f16 g_w10[(size_t)Lnum*Dm*Ff], g_w11[(size_t)Lnum*Dm*Ff];
__device__ __align__(256) f16 g_w20[(size_t)Lnum*Dm*Ff], g_w21[(size_t)Lnum*Dm*Ff];
__device__ __align__(256) f16 g_cb0[Kcb*Dm], g_cb1[Kcb*Dm];

// ---------------- helpers ----------------------------------------------------
__device__ __forceinline__ void split2(float v, f16& h, f16& l) {
    h = __float2half_rn(v);
    float r = v - __half2float(h);
    l = __float2half_rn(r);
}
__device__ __forceinline__ void st_f162(f16* p, f16 a, f16 b) {
    __half2 t; t.x = a; t.y = b;
    *reinterpret_cast<__half2*>(p) = t;
}
__device__ __forceinline__ void split2_store4(float4 v, f16* a0, f16* a1, size_t o) {
    f16 h[4], l[4];
    split2(v.x, h[0], l[0]); split2(v.y, h[1], l[1]);
    split2(v.z, h[2], l[2]); split2(v.w, h[3], l[3]);
    st_f162(a0 + o, h[0], h[1]); st_f162(a0 + o + 2, h[2], h[3]);
    st_f162(a1 + o, l[0], l[1]); st_f162(a1 + o + 2, l[2], l[3]);
}
__device__ __forceinline__ uint32_t smem_u32(const void* p) {
    return (uint32_t)__cvta_generic_to_shared(p);
}
__device__ __forceinline__ uint32_t elect_one() {
    uint32_t pred;
    asm volatile("{\n\t.reg .pred p;\n\telect.sync _|p, 0xFFFFFFFF;\n\tselp.b32 %0, 1, 0, p;\n\t}"
                 : "=r"(pred));
    return pred;
}
__device__ __forceinline__ void mwait(uint32_t a, uint32_t p) {
    asm volatile("{\n\t.reg .pred P;\n\tWL_%=:\n\t"
                 "mbarrier.try_wait.parity.acquire.cta.shared::cta.b64 P, [%0], %1, 0x989680;\n\t"
                 "@P bra WD_%=;\n\tbra WL_%=;\n\tWD_%=:\n\t}" :: "r"(a), "r"(p) : "memory");
}
#if HAS_TCGEN05
__device__ __forceinline__ void mma_f16_ss(uint32_t d, uint64_t a, uint64_t b, uint32_t en) {
    asm volatile("{\n\t.reg .pred p;\n\tsetp.ne.u32 p, %4, 0;\n\t"
                 "tcgen05.mma.cta_group::1.kind::f16 [%0], %1, %2, %3, {%5, %5, %5, %5}, p;\n\t}"
                 :: "r"(d), "l"(a), "l"(b), "r"(IDESC_FP16), "r"(en), "r"(0u) : "memory");
}
#define LDTM_X32(r, addr) \
    asm volatile("tcgen05.ld.sync.aligned.32x32b.x32.b32 " \
        "{%0,%1,%2,%3,%4,%5,%6,%7,%8,%9,%10,%11,%12,%13,%14,%15," \
        "%16,%17,%18,%19,%20,%21,%22,%23,%24,%25,%26,%27,%28,%29,%30,%31}, [%32];" \
        : "=r"((r)[0]),"=r"((r)[1]),"=r"((r)[2]),"=r"((r)[3]),"=r"((r)[4]),"=r"((r)[5]),"=r"((r)[6]),"=r"((r)[7]), \
          "=r"((r)[8]),"=r"((r)[9]),"=r"((r)[10]),"=r"((r)[11]),"=r"((r)[12]),"=r"((r)[13]),"=r"((r)[14]),"=r"((r)[15]), \
          "=r"((r)[16]),"=r"((r)[17]),"=r"((r)[18]),"=r"((r)[19]),"=r"((r)[20]),"=r"((r)[21]),"=r"((r)[22]),"=r"((r)[23]), \
          "=r"((r)[24]),"=r"((r)[25]),"=r"((r)[26]),"=r"((r)[27]),"=r"((r)[28]),"=r"((r)[29]),"=r"((r)[30]),"=r"((r)[31]) \
        : "r"(addr))
#endif

__device__ __forceinline__ float blockReduceSum(float v, float* sh) {
#pragma unroll
    for (int off = 16; off > 0; off >>= 1) v += __shfl_xor_sync(0xffffffffu, v, off);
    int warp = threadIdx.x >> 5, lane = threadIdx.x & 31;
    if (lane == 0) sh[warp] = v;
    __syncthreads();
    if (threadIdx.x == 0) {
        float s = 0.f; int nw = blockDim.x >> 5;
        for (int i = 0; i < nw; i++) s += sh[i];
        sh[0] = s;
    }
    __syncthreads();
    float r = sh[0];
    __syncthreads();
    return r;
}
__device__ __forceinline__ float gelu_exact(float v) {
    return 0.5f * v * (1.0f + erff(v * 0.70710678118654752f));
}

// ---------------- GEMM: C = A @ B^T (A,B = 2-plane fp16 splits) --------------
#if HAS_TCGEN05
__device__ __forceinline__ void ldtile(char* dst, const f16* src, int Kd, int r0, int k0, int tid) {
#pragma unroll
    for (int j = 0; j < 4; j++) {
        int s = tid + j * 256;             // 0..1023
        int r = s >> 3, cb = s & 7;
        uint32_t off = (uint32_t)((r << 7) | (cb << 4));
        off ^= (off >> 3) & 0x70;
        *(uint4*)(dst + off) = *(const uint4*)(src + (size_t)(r0 + r) * Kd + k0 + cb * 8);
    }
}
__device__ __forceinline__ void load_stage(char* st, const f16* A0, const f16* A1,
                                           const f16* B0, const f16* B1,
                                           int Kd, int row0, int col0, int k0, int tid) {
    ldtile(st,              A0, Kd, row0, k0, tid);
    ldtile(st + TILE_B,     A1, Kd, row0, k0, tid);
    ldtile(st + 2 * TILE_B, B0, Kd, col0,       k0, tid);
    ldtile(st + 3 * TILE_B, B0, Kd, col0 + 128, k0, tid);
    ldtile(st + 4 * TILE_B, B1, Kd, col0,       k0, tid);
    ldtile(st + 5 * TILE_B, B1, Kd, col0 + 128, k0, tid);
}
#endif

__global__ void __launch_bounds__(256, 1) __cluster_dims__(1, 1, 1)
gemm_tc(const f16* __restrict__ A0, const f16* __restrict__ A1,
        const f16* __restrict__ B0, const f16* __restrict__ B1,
        const float* __restrict__ bias,
        float* __restrict__ outf, int* __restrict__ outi,
        f16* __restrict__ o0, f16* __restrict__ o1,
        int Kd, int Ntot, int act) {
    extern __shared__ char sm[];
    int tid = threadIdx.x, wid = tid >> 5, lane = tid & 31;
    int row0 = blockIdx.y * BM, col0 = blockIdx.x * BN;
#if HAS_TCGEN05
    uint32_t sbase = smem_u32(sm);
    if (wid == 0) {
        asm volatile("tcgen05.alloc.cta_group::1.sync.aligned.shared::cta.b32 [%0], %1;"
                     :: "r"(sbase), "r"(256u) : "memory");
    }
    if (tid == 0) {
        asm volatile("mbarrier.init.shared.b64 [%0], %1;" :: "r"(sbase + 8), "r"(1u) : "memory");
        asm volatile("mbarrier.init.shared.b64 [%0], %1;" :: "r"(sbase + 16), "r"(1u) : "memory");
    }
    __syncthreads();
    uint32_t dt;
    asm volatile("ld.shared.b32 %0, [%1];" : "=r"(dt) : "r"(sbase));

    uint32_t s0off = ((sbase + 1024 + 1023) & ~1023u) - sbase;
    char* st0 = sm + s0off;
    char* st1 = st0 + STAGE_BYTES;
    uint32_t stb0 = sbase + s0off;
    const int NK = Kd >> 6;

    load_stage(st0, A0, A1, B0, B1, Kd, row0, col0, 0, tid);
    __syncthreads();
    uint32_t ph0 = 0, ph1 = 0;

    for (int k = 0; k < NK; k++) {
        uint32_t stb = stb0 + (uint32_t)(k & 1) * STAGE_BYTES;
        if (wid == 0) {
            asm volatile("fence.proxy.async.shared::cta;" ::: "memory");
            if (elect_one()) {
                uint64_t da0 = DESC_BASE | ((uint64_t)(stb >> 4) & 0x3FFF);
                uint64_t da1 = DESC_BASE | ((uint64_t)((stb + TILE_B) >> 4) & 0x3FFF);
#pragma unroll
                for (int nb = 0; nb < 4; nb++) {       // four N=64 column blocks
                    uint32_t d = dt + nb * 64;
                    uint32_t sub = (uint32_t)(nb >> 1) * TILE_B;  // 128-row sub-tile
                    uint64_t db0 = DESC_BASE | ((uint64_t)((stb + 2 * TILE_B + sub) >> 4) & 0x3FFF);
                    uint64_t db1 = DESC_BASE | ((uint64_t)((stb + 4 * TILE_B + sub) >> 4) & 0x3FFF);
                    uint64_t bo = (uint64_t)((nb & 1) * 512);     // 64 rows * 128B in 16B units
#pragma unroll
                    for (int kk = 0; kk < 4; kk++) {   // K=16 per MMA
                        uint64_t ao = (uint64_t)(kk * 2);
                        uint64_t bk = bo + kk * 2;
                        uint32_t en = (k > 0) || (kk > 0);
                        mma_f16_ss(d, da0 + ao, db0 + bk, en);   // hh
                        mma_f16_ss(d, da0 + ao, db1 + bk, 1u);   // hl
                        mma_f16_ss(d, da1 + ao, db0 + bk, 1u);   // lh
                    }
                }
                asm volatile("tcgen05.commit.cta_group::1.mbarrier::arrive::one.shared::cluster.b64 [%0];"
                             :: "r"(sbase + 8 + (uint32_t)(k & 1) * 8) : "memory");
            }
        }
        if (k + 1 < NK) {
            if (k >= 1) {
                if (((k + 1) & 1) == 0) { mwait(sbase + 8, ph0); ph0 ^= 1; }
                else                    { mwait(sbase + 16, ph1); ph1 ^= 1; }
            }
            load_stage((k & 1) ? st0 : st1, A0, A1, B0, B1, Kd, row0, col0, (k + 1) << 6, tid);
        }
        __syncthreads();
    }
    if (((NK - 1) & 1) == 0) { mwait(sbase + 8, ph0); }
    else                     { mwait(sbase + 16, ph1); }
    asm volatile("tcgen05.fence::after_thread_sync;" ::: "memory");

    if (wid < 4) {
        int row = row0 + wid * 32 + lane;
        if (act == 2) {
            float best = 3.4e38f; int bi = 0;
            for (int c0 = 0; c0 < 8; c0++) {
                uint32_t r[32];
                LDTM_X32(r, dt + c0 * 32);
                asm volatile("tcgen05.wait::ld.sync.aligned;" ::: "memory");
#pragma unroll
                for (int j = 0; j < 32; j++) {
                    int code = col0 + c0 * 32 + j;
                    float d = __ldg(bias + code) - 2.0f * __uint_as_float(r[j]);
                    if (d < best) { best = d; bi = code; }
                }
            }
            outf[(size_t)row * gridDim.x + blockIdx.x] = best;
            outi[(size_t)row * gridDim.x + blockIdx.x] = bi;
        } else if (act == 1) {
            for (int c0 = 0; c0 < 8; c0++) {
                uint32_t r[32];
                LDTM_X32(r, dt + c0 * 32);
                asm volatile("tcgen05.wait::ld.sync.aligned;" ::: "memory");
                size_t base = (size_t)row * Ntot + col0 + c0 * 32;
#pragma unroll
                for (int j2 = 0; j2 < 16; j2++) {
                    int c = c0 * 32 + j2 * 2;
                    float v0 = gelu_exact(__uint_as_float(r[j2 * 2])     + __ldg(bias + col0 + c));
                    float v1 = gelu_exact(__uint_as_float(r[j2 * 2 + 1]) + __ldg(bias + col0 + c + 1));
                    f16 h0, l0, h1, l1;
                    split2(v0, h0, l0); split2(v1, h1, l1);
                    st_f162(o0 + base + j2 * 2, h0, h1);
                    st_f162(o1 + base + j2 * 2, l0, l1);
                }
            }
        } else {
            for (int c0 = 0; c0 < 8; c0++) {
                uint32_t r[32];
                LDTM_X32(r, dt + c0 * 32);
                asm volatile("tcgen05.wait::ld.sync.aligned;" ::: "memory");
                size_t base = (size_t)row * Ntot + col0 + c0 * 32;
#pragma unroll
                for (int j4 = 0; j4 < 8; j4++) {
                    float4 ov; float* op = &ov.x;
#pragma unroll
                    for (int j = 0; j < 4; j++)
                        op[j] = __uint_as_float(r[j4 * 4 + j]) + __ldg(bias + col0 + c0 * 32 + j4 * 4 + j);
                    *(float4*)(outf + base + j4 * 4) = ov;
                }
            }
        }
    }
    __syncthreads();
    if (tid == 0) {
        asm volatile("mbarrier.inval.shared.b64 [%0];" :: "r"(sbase + 8) : "memory");
        asm volatile("mbarrier.inval.shared.b64 [%0];" :: "r"(sbase + 16) : "memory");
    }
    if (wid == 0) {
        asm volatile("tcgen05.relinquish_alloc_permit.cta_group::1.sync.aligned;");
        asm volatile("tcgen05.dealloc.cta_group::1.sync.aligned.b32 %0, %1;" :: "r"(dt), "r"(256u));
    }
#else
    // ---------- portable fp32 FFMA fallback (identical semantics) ----------
    const int W = 132;
    float* As = (float*)sm;
    float* Bs = As + 16 * W;
    int tx = tid & 15, ty = tid >> 4;
    float runb[8]; int runi[8];
#pragma unroll
    for (int i = 0; i < 8; i++) { runb[i] = 3.4e38f; runi[i] = 0; }
    float carry = 3.4e38f; int carryi = 0;
    for (int nh = 0; nh < 2; nh++) {
        int ch0 = col0 + nh * 128;
        float acc[8][8] = {};
        for (int k0 = 0; k0 < Kd; k0 += 16) {
            __syncthreads();
#pragma unroll
            for (int j = 0; j < 8; j++) {
                int s = tid + j * 256; int m = s & 127, kk = s >> 7;
                size_t ga = (size_t)(row0 + m) * Kd + k0 + kk;
                As[kk * W + m] = __half2float(A0[ga]) + __half2float(A1[ga]);
                size_t gb = (size_t)(ch0 + m) * Kd + k0 + kk;
                Bs[kk * W + m] = __half2float(B0[gb]) + __half2float(B1[gb]);
            }
            __syncthreads();
#pragma unroll
            for (int kk = 0; kk < 16; kk++) {
                float a[8], b[8];
#pragma unroll
                for (int i = 0; i < 8; i++) a[i] = As[kk * W + ty * 8 + i];
#pragma unroll
                for (int j = 0; j < 8; j++) b[j] = Bs[kk * W + tx * 8 + j];
#pragma unroll
                for (int i = 0; i < 8; i++)
#pragma unroll
                    for (int j = 0; j < 8; j++) acc[i][j] += a[i] * b[j];
            }
        }
        if (act == 2) {
#pragma unroll
            for (int i = 0; i < 8; i++)
#pragma unroll
                for (int j = 0; j < 8; j++) {
                    int code = ch0 + tx * 8 + j;
                    float d = __ldg(bias + code) - 2.0f * acc[i][j];
                    if (d < runb[i]) { runb[i] = d; runi[i] = code; }
                }
            __syncthreads();
            float* bvs = (float*)sm;
            int*   bis = (int*)(sm + 8192);
#pragma unroll
            for (int i = 0; i < 8; i++) { bvs[(ty * 8 + i) * 16 + tx] = runb[i]; bis[(ty * 8 + i) * 16 + tx] = runi[i]; }
            __syncthreads();
            if (tid < 128) {
                float bb = bvs[tid * 16]; int bi = bis[tid * 16];
                for (int t2 = 1; t2 < 16; t2++) {
                    float v = bvs[tid * 16 + t2]; int c = bis[tid * 16 + t2];
                    if (v < bb || (v == bb && c < bi)) { bb = v; bi = c; }
                }
                if (bb < carry) { carry = bb; carryi = bi; }
            }
            __syncthreads();
        } else if (act == 1) {
#pragma unroll
            for (int i = 0; i < 8; i++) {
                size_t base = (size_t)(row0 + ty * 8 + i) * Ntot + ch0 + tx * 8;
#pragma unroll
                for (int j = 0; j < 8; j++) {
                    float v = gelu_exact(acc[i][j] + __ldg(bias + ch0 + tx * 8 + j));
                    f16 h, l; split2(v, h, l);
                    o0[base + j] = h; o1[base + j] = l;
                }
            }
        } else {
#pragma unroll
            for (int i = 0; i < 8; i++) {
                size_t base = (size_t)(row0 + ty * 8 + i) * Ntot + ch0 + tx * 8;
#pragma unroll
                for (int j = 0; j < 8; j++)
                    outf[base + j] = acc[i][j] + __ldg(bias + ch0 + tx * 8 + j);
            }
        }
    }
    if (act == 2 && tid < 128) {
        outf[(size_t)(row0 + tid) * gridDim.x + blockIdx.x] = carry;
        outi[(size_t)(row0 + tid) * gridDim.x + blockIdx.x] = carryi;
    }
#endif
}

// ------------- batched weight split+transpose (all 24 matrices, one launch) --
// Per layer: r in [0,3072): [0,256) Wq, [256,512) Wk, [512,768) Wv,
// [768,1024) Wo (all 512x512 -> 256 tiles), [1024,2048) W1 (512x2048, 1024 tiles),
// [2048,3072) W2 (2048x512, 1024 tiles). Same per-tile math as the old tsplit.
__global__ void tsplit_all(const float* __restrict__ Wq, const float* __restrict__ Wk,
                           const float* __restrict__ Wv, const float* __restrict__ Wo,
                           const float* __restrict__ W1, const float* __restrict__ W2) {
    __shared__ float t[32][33];
    int id = blockIdx.x;
    int l = id / 3072, r = id % 3072;
    const float* src; f16* d0; f16* d1;
    int Kd, Nd, tile;
    if (r < 1024) {
        tile = r & 255; Kd = 512; Nd = 512;
        size_t off = (size_t)l * DD;
        int m = r >> 8;
        if (m == 0)      { src = Wq + off; d0 = g_wq0 + off; d1 = g_wq1 + off; }
        else if (m == 1) { src = Wk + off; d0 = g_wk0 + off; d1 = g_wk1 + off; }
        else if (m == 2) { src = Wv + off; d0 = g_wv0 + off; d1 = g_wv1 + off; }
        else             { src = Wo + off; d0 = g_wo0 + off; d1 = g_wo1 + off; }
    } else if (r < 2048) {
        tile = r - 1024; Kd = 512; Nd = 2048;
        size_t off = (size_t)l * Dm * Ff;
        src = W1 + off; d0 = g_w10 + off; d1 = g_w11 + off;
    } else {
        tile = r - 2048; Kd = 2048; Nd = 512;
        size_t off = (size_t)l * Dm * Ff;
        src = W2 + off; d0 = g_w20 + off; d1 = g_w21 + off;
    }
    int nb = Nd >> 5;
    int n0 = (tile % nb) << 5, k0 = (tile / nb) << 5;
    int tx = threadIdx.x, ty = threadIdx.y;  // (32,8)
#pragma unroll
    for (int i = 0; i < 4; i++) {
        int k = ty + i * 8;
        t[k][tx] = src[(size_t)(k0 + k) * Nd + n0 + tx];
    }
    __syncthreads();
#pragma unroll
    for (int i = 0; i < 4; i++) {
        int n = ty + i * 8;
        f16 h, l2; split2(t[tx][n], h, l2);
        size_t o = (size_t)(n0 + n) * Kd + k0 + tx;
        d0[o] = h; d1[o] = l2;
    }
}

__global__ void esplit(const float* __restrict__ X, f16* __restrict__ O0,
                       f16* __restrict__ O1, int n) {
    int i = blockIdx.x * blockDim.x + threadIdx.x;
    if (i >= n) return;
    f16 h, l; split2(X[i], h, l);
    O0[i] = h; O1[i] = l;
}

// ---------------- embedding gather (+split) ----------------------------------
__global__ void embed_kernel(const int* __restrict__ ids, const float* __restrict__ emb) {
    int i = blockIdx.x * blockDim.x + threadIdx.x;
    if (i >= Mrows * 128) return;
    int row = i >> 7, c4 = (i & 127) << 2;
    float4 v = *(const float4*)(emb + (size_t)ids[row] * Dm + c4);
    size_t o = (size_t)row * Dm + c4;
    *(float4*)(g_x + o) = v;
    split2_store4(v, g_x0, g_x1, o);
}

// ---------------- RoPE --------------------------------------------------------
__global__ void rope_tables() {
    int i = blockIdx.x * blockDim.x + threadIdx.x;
    if (i >= Tseq * 32) return;
    int t = i >> 5, j = i & 31;
    float invf = 1.0f / powf(10000.0f, (2.0f * (float)j) / 64.0f);
    float ang = (float)t * invf;
    g_cos[i] = cosf(ang); g_sin[i] = sinf(ang);
}

__global__ void rope_apply() {
    int i = blockIdx.x * blockDim.x + threadIdx.x;
    if (i >= Mrows * Hn * 32) return;
    int j = i & 31, h = (i >> 5) & 7, bt = i >> 8, t = bt & (Tseq - 1);
    float c = g_cos[(t << 5) + j], s = g_sin[(t << 5) + j];
    size_t base = ((size_t)bt * Hn + h) * HDim;
    float q1 = g_q[base + j], q2 = g_q[base + j + 32];
    g_q[base + j] = q1 * c - q2 * s; g_q[base + j + 32] = q2 * c + q1 * s;
    float k1 = g_k[base + j], k2 = g_k[base + j + 32];
    g_k[base + j] = k1 * c - k2 * s; g_k[base + j + 32] = k2 * c + k1 * s;
}

// ---------------- attention (fp32 flash, 128q x 128k tiles, 8x8 microtile) ----
__global__ void __launch_bounds__(256, 1)
attention_kernel() {
    extern __shared__ float as_[];
    float* Qts = as_;                         // [64][132] (d, q)
    float* Kts = as_ + 64 * 132;              // [64][132] (d, k)
    float* Vs  = as_ + 2 * 64 * 132;          // [128][68] (k, d)
    float* Ps  = as_ + 2 * 64 * 132 + 128 * 68;  // [128][132] (q, k)
    int qt = blockIdx.x, h = blockIdx.y, b = blockIdx.z;
    int tid = threadIdx.x, tx = tid & 15, ty = tid >> 4;
    int t0 = qt * 128;
    // load Q^T (128 rows x 64 d)
    for (int it = tid; it < 2048; it += 256) {
        int r = it >> 4, d4 = (it & 15) << 2;
        float4 v = *(const float4*)(g_q + (size_t)(b * Tseq + t0 + r) * Dm + h * HDim + d4);
        Qts[(d4 + 0) * 132 + r] = v.x; Qts[(d4 + 1) * 132 + r] = v.y;
        Qts[(d4 + 2) * 132 + r] = v.z; Qts[(d4 + 3) * 132 + r] = v.w;
    }
    float m[8], l[8], o[8][4];
#pragma unroll
    for (int i = 0; i < 8; i++) {
        m[i] = -1e30f; l[i] = 0.f;
#pragma unroll
        for (int j = 0; j < 4; j++) o[i][j] = 0.f;
    }
    for (int kt = 0; kt < 4; kt++) {
        __syncthreads();   // prev PV (reads Ps, Vs) done; Q load done at kt=0
        int k0 = kt * 128;
        for (int it = tid; it < 2048; it += 256) {
            int r = it >> 4, d4 = (it & 15) << 2;
            size_t gb = (size_t)(b * Tseq + k0 + r) * Dm + h * HDim + d4;
            float4 kv = *(const float4*)(g_k + gb);
            Kts[(d4 + 0) * 132 + r] = kv.x; Kts[(d4 + 1) * 132 + r] = kv.y;
            Kts[(d4 + 2) * 132 + r] = kv.z; Kts[(d4 + 3) * 132 + r] = kv.w;
            *(float4*)&Vs[r * 68 + d4] = *(const float4*)(g_v + gb);
        }
        __syncthreads();
        float s[8][8] = {};
        for (int d = 0; d < 64; d++) {
            float a[8], bb[8];
            *(float4*)&a[0]  = *(float4*)&Qts[d * 132 + ty * 8];
            *(float4*)&a[4]  = *(float4*)&Qts[d * 132 + ty * 8 + 4];
            *(float4*)&bb[0] = *(float4*)&Kts[d * 132 + tx * 8];
            *(float4*)&bb[4] = *(float4*)&Kts[d * 132 + tx * 8 + 4];
#pragma unroll
            for (int i = 0; i < 8; i++)
#pragma unroll
                for (int j = 0; j < 8; j++) s[i][j] += a[i] * bb[j];
        }
#pragma unroll
        for (int i = 0; i < 8; i++) {
#pragma unroll
            for (int j = 0; j < 8; j++) s[i][j] *= 0.125f;
            float rm = s[i][0];
#pragma unroll
            for (int j = 1; j < 8; j++) rm = fmaxf(rm, s[i][j]);
#pragma unroll
            for (int off = 8; off > 0; off >>= 1) rm = fmaxf(rm, __shfl_xor_sync(0xffffffffu, rm, off));
            float mn = fmaxf(m[i], rm);
            float corr = expf(m[i] - mn);
            float rs = 0.f;
#pragma unroll
            for (int j = 0; j < 8; j++) { s[i][j] = expf(s[i][j] - mn); rs += s[i][j]; }
#pragma unroll
            for (int off = 8; off > 0; off >>= 1) rs += __shfl_xor_sync(0xffffffffu, rs, off);
            l[i] = l[i] * corr + rs;
#pragma unroll
            for (int j = 0; j < 4; j++) o[i][j] *= corr;
            m[i] = mn;
            *(float4*)&Ps[(ty * 8 + i) * 132 + tx * 8]     = make_float4(s[i][0], s[i][1], s[i][2], s[i][3]);
            *(float4*)&Ps[(ty * 8 + i) * 132 + tx * 8 + 4] = make_float4(s[i][4], s[i][5], s[i][6], s[i][7]);
        }
        __syncthreads();   // P complete before PV reads
        for (int k2 = 0; k2 < 128; k2++) {
            float4 bv = *(float4*)&Vs[k2 * 68 + tx * 4];
#pragma unroll
            for (int i = 0; i < 8; i++) {
                float a = Ps[(ty * 8 + i) * 132 + k2];
                o[i][0] += a * bv.x; o[i][1] += a * bv.y;
                o[i][2] += a * bv.z; o[i][3] += a * bv.w;
            }
        }
    }
#pragma unroll
    for (int i = 0; i < 8; i++) {
        float inv = 1.0f / l[i];
        float4 ov = make_float4(o[i][0] * inv, o[i][1] * inv, o[i][2] * inv, o[i][3] * inv);
        size_t ob = (size_t)(b * Tseq + t0 + ty * 8 + i) * Dm + h * HDim + tx * 4;
        split2_store4(ov, g_a0, g_a1, ob);
    }
}

// ---------------- residual add + LayerNorm (writes x + split2) ----------------
__global__ void add_ln(float* __restrict__ x, const float* __restrict__ r,
                       const float* __restrict__ g, const float* __restrict__ b) {
    __shared__ float sh[8];
    int row = blockIdx.x, tid = threadIdx.x;
    size_t base = (size_t)row * Dm + (tid << 2);
    float4 xv = *(float4*)(x + base);
    float4 rv = *(const float4*)(r + base);
    float v0 = xv.x + rv.x, v1 = xv.y + rv.y, v2 = xv.z + rv.z, v3 = xv.w + rv.w;
    float mean = blockReduceSum(v0 + v1 + v2 + v3, sh) * (1.0f / Dm);
    float d0 = v0 - mean, d1 = v1 - mean, d2 = v2 - mean, d3 = v3 - mean;
    float var = blockReduceSum(d0 * d0 + d1 * d1 + d2 * d2 + d3 * d3, sh) * (1.0f / Dm);
    float inv = rsqrtf(var + 1e-5f);
    int c = tid << 2;
    float4 ov;
    ov.x = d0 * inv * g[c] + b[c];         ov.y = d1 * inv * g[c + 1] + b[c + 1];
    ov.z = d2 * inv * g[c + 2] + b[c + 2]; ov.w = d3 * inv * g[c + 3] + b[c + 3];
    *(float4*)(x + base) = ov;
    split2_store4(ov, g_x0, g_x1, base);
}

// ---------------- VQ helpers ---------------------------------------------------
__global__ void cnorm_kernel(const float* __restrict__ cbp) {
    __shared__ float sh[8];
    int code = blockIdx.x, tid = threadIdx.x;
    float4 v = *(const float4*)(cbp + (size_t)code * Dm + (tid << 2));
    float s = blockReduceSum(v.x * v.x + v.y * v.y + v.z * v.z + v.w * v.w, sh);
    if (tid == 0) g_cnorm[code] = s;
}

__global__ void vq_reduce() {
    int row = blockIdx.x * blockDim.x + threadIdx.x;
    if (row >= Mrows) return;
    float b = g_pb[(size_t)row * 32]; int bi = g_pi[(size_t)row * 32];
    for (int t = 1; t < 32; t++) {
        float v = g_pb[(size_t)row * 32 + t];
        int   c = g_pi[(size_t)row * 32 + t];
        if (v < b || (v == b && c < bi)) { b = v; bi = c; }
    }
    g_idx[row] = bi;
}

__global__ void vq_out(const float* __restrict__ cbp, float* __restrict__ out, int writeIdx) {
    __shared__ float sh[8];
    int row = blockIdx.x, tid = threadIdx.x;
    int id = g_idx[row];
    size_t zb = (size_t)row * Dm + (tid << 2);
    float4 z = *(const float4*)(g_x + zb);
    float4 c = *(const float4*)(cbp + (size_t)id * Dm + (tid << 2));
    float4 q;
    q.x = z.x + (c.x - z.x); q.y = z.y + (c.y - z.y);
    q.z = z.z + (c.z - z.z); q.w = z.w + (c.w - z.w);
    *(float4*)(out + zb) = q;
    float dx = z.x - c.x, dy = z.y - c.y, dz = z.z - c.z, dw = z.w - c.w;
    float s = blockReduceSum(dx * dx + dy * dy + dz * dz + dw * dw, sh);
    if (tid == 0) {
        g_lpart[row] = s;
        if (writeIdx) out[(size_t)Mrows * Dm + row] = (float)id;
    }
}

__global__ void loss_final(float* __restrict__ out, int writeLoss, size_t off) {
    __shared__ float sh[8];
    int tid = threadIdx.x;
    float s = 0.f;
    for (int i = tid; i < Mrows; i += 256) s += g_lpart[i];
    s = blockReduceSum(s, sh);
    if (tid == 0 && writeLoss) out[off] = 0.3f * s / (float)((size_t)Mrows * Dm);
}

// ---------------- host orchestration ------------------------------------------
extern "C" void kernel_launch(void* const* d_in, const int* in_sizes, int n_in,
                              void* d_out, int out_size) {
    const int*   ids  = (const int*)  d_in[0];
    const float* emb  = (const float*)d_in[1];
    const float* Wq   = (const float*)d_in[2];
    const float* bq   = (const float*)d_in[3];
    const float* Wk   = (const float*)d_in[4];
    const float* bk   = (const float*)d_in[5];
    const float* Wv   = (const float*)d_in[6];
    const float* bv   = (const float*)d_in[7];
    const float* Wo   = (const float*)d_in[8];
    const float* bo   = (const float*)d_in[9];
    const float* ln1g = (const float*)d_in[10];
    const float* ln1b = (const float*)d_in[11];
    const float* W1   = (const float*)d_in[12];
    const float* b1   = (const float*)d_in[13];
    const float* W2   = (const float*)d_in[14];
    const float* b2   = (const float*)d_in[15];
    const float* ln2g = (const float*)d_in[16];
    const float* ln2b = (const float*)d_in[17];
    const float* cb   = (const float*)d_in[18];
    float* out = (float*)d_out;

    cudaFuncSetAttribute(gemm_tc, cudaFuncAttributeMaxDynamicSharedMemorySize, SMEM_DYN);
    cudaFuncSetAttribute(attention_kernel, cudaFuncAttributeMaxDynamicSharedMemorySize, ATT_SMEM);

    float *px, *pq, *pk, *pv, *po, *pcn, *ppb;
    int *ppi;
    f16 *x0, *x1, *a0, *a1, *h0, *h1;
    f16 *wq0, *wq1, *wk0, *wk1, *wv0, *wv1, *wo0, *wo1;
    f16 *w10, *w11, *w20, *w21, *cb0, *cb1;
    cudaGetSymbolAddress((void**)&px, g_x);
    cudaGetSymbolAddress((void**)&pq, g_q);   cudaGetSymbolAddress((void**)&pk, g_k);
    cudaGetSymbolAddress((void**)&pv, g_v);   cudaGetSymbolAddress((void**)&po, g_o);
    cudaGetSymbolAddress((void**)&pcn, g_cnorm);
    cudaGetSymbolAddress((void**)&ppb, g_pb); cudaGetSymbolAddress((void**)&ppi, g_pi);
    cudaGetSymbolAddress((void**)&x0, g_x0);  cudaGetSymbolAddress((void**)&x1, g_x1);
    cudaGetSymbolAddress((void**)&a0, g_a0);  cudaGetSymbolAddress((void**)&a1, g_a1);
    cudaGetSymbolAddress((void**)&h0, g_h0);  cudaGetSymbolAddress((void**)&h1, g_h1);
    cudaGetSymbolAddress((void**)&wq0, g_wq0); cudaGetSymbolAddress((void**)&wq1, g_wq1);
    cudaGetSymbolAddress((void**)&wk0, g_wk0); cudaGetSymbolAddress((void**)&wk1, g_wk1);
    cudaGetSymbolAddress((void**)&wv0, g_wv0); cudaGetSymbolAddress((void**)&wv1, g_wv1);
    cudaGetSymbolAddress((void**)&wo0, g_wo0); cudaGetSymbolAddress((void**)&wo1, g_wo1);
    cudaGetSymbolAddress((void**)&w10, g_w10); cudaGetSymbolAddress((void**)&w11, g_w11);
    cudaGetSymbolAddress((void**)&w20, g_w20); cudaGetSymbolAddress((void**)&w21, g_w21);
    cudaGetSymbolAddress((void**)&cb0, g_cb0); cudaGetSymbolAddress((void**)&cb1, g_cb1);

    dim3 tb(32, 8);
    tsplit_all<<<Lnum * 3072, tb>>>(Wq, Wk, Wv, Wo, W1, W2);
    esplit<<<(Kcb * Dm + 255) / 256, 256>>>(cb, cb0, cb1, Kcb * Dm);
    cnorm_kernel<<<Kcb, 128>>>(cb);
    rope_tables<<<(Tseq * 32 + 255) / 256, 256>>>();
    embed_kernel<<<(Mrows * 128 + 255) / 256, 256>>>(ids, emb);

    dim3 gDD(Dm / BN, Mrows / BM);    // (2,128)
    dim3 gDF(Ff / BN, Mrows / BM);    // (8,128)
    dim3 gVQ(Kcb / BN, Mrows / BM);   // (32,128)
    for (int l = 0; l < Lnum; l++) {
        size_t wo_off = (size_t)l * DD, f_off = (size_t)l * Dm * Ff;
        gemm_tc<<<gDD, 256, SMEM_DYN>>>(x0, x1, wq0 + wo_off, wq1 + wo_off,
                                        bq + l * Dm, pq, 0, 0, 0, Dm, Dm, 0);
        gemm_tc<<<gDD, 256, SMEM_DYN>>>(x0, x1, wk0 + wo_off, wk1 + wo_off,
                                        bk + l * Dm, pk, 0, 0, 0, Dm, Dm, 0);
        gemm_tc<<<gDD, 256, SMEM_DYN>>>(x0, x1, wv0 + wo_off, wv1 + wo_off,
                                        bv + l * Dm, pv, 0, 0, 0, Dm, Dm, 0);
        rope_apply<<<(Mrows * Hn * 32 + 255) / 256, 256>>>();
        attention_kernel<<<dim3(Tseq / 128, Hn, Bsz), 256, ATT_SMEM>>>();
        gemm_tc<<<gDD, 256, SMEM_DYN>>>(a0, a1, wo0 + wo_off, wo1 + wo_off,
                                        bo + l * Dm, po, 0, 0, 0, Dm, Dm, 0);
        add_ln<<<Mrows, 128>>>(px, po, ln1g + l * Dm, ln1b + l * Dm);
        gemm_tc<<<gDF, 256, SMEM_DYN>>>(x0, x1, w10 + f_off, w11 + f_off,
                                        b1 + l * Ff, 0, 0, h0, h1, Dm, Ff, 1);
        gemm_tc<<<gDD, 256, SMEM_DYN>>>(h0, h1, w20 + f_off, w21 + f_off,
                                        b2 + l * Dm, po, 0, 0, 0, Ff, Dm, 0);
        add_ln<<<Mrows, 128>>>(px, po, ln2g + l * Dm, ln2b + l * Dm);
    }

    gemm_tc<<<gVQ, 256, SMEM_DYN>>>(x0, x1, cb0, cb1, pcn, ppb, ppi, 0, 0, Dm, Kcb, 2);
    vq_reduce<<<(Mrows + 255) / 256, 256>>>();

    size_t quantN = (size_t)Mrows * Dm;
    int writeIdx = (out_size >= (int)(quantN + Mrows)) ? 1 : 0;
    int writeLoss = 0;
    size_t lossOff = quantN + Mrows;
    if (out_size >= (int)(quantN + Mrows + 1)) { writeLoss = 1; lossOff = quantN + Mrows; }
    else if (out_size == (int)(quantN + 1))    { writeLoss = 1; lossOff = quantN; }

    vq_out<<<Mrows, 128>>>(cb, out, writeIdx);
    loss_final<<<1, 256>>>(out, writeLoss, lossOff);
}

// round 17
// speedup vs baseline: 1.0180x; 1.0180x over previous
#include <cuda_runtime.h>
#include <cuda_fp16.h>
#include <math.h>
#include <stdint.h>

#define Bsz  32
#define Tseq 512
#define Dm   512
#define Lnum 4
#define Hn   8
#define HDim 64
#define Ff   2048
#define Kcb  8192
#define Mrows (Bsz*Tseq)   // 16384
#define DD (Dm*Dm)

// GEMM tiling: 128x256 tile, BK=64, 2-plane fp16 split, TMEM 256 cols
#define BM 128
#define BN 256
#define TILE_B 16384                       // one 128x64 fp16 tile, SW128 (128B rows)
#define STAGE_BYTES (6*TILE_B)             // A0,A1 (2) + B0,B1 (4 sub-tiles) = 98304
#define SMEM_DYN (2048 + 2*STAGE_BYTES)    // 198656
// idesc kind::f16: F32 acc(1<<4), FP16 a/b, N=64 (8<<17), M=128 (8<<24)
#define IDESC_FP16 ((1u<<4)|(8u<<17)|(8u<<24))
#define DESC_BASE 0x4000404000010000ull    // SW128, version=1, SBO=64, LBO=1
// attention smem: Q^T[64][132] + K^T[64][132] + V[128][68] + P[128][132]
#define ATT_SMEM ((2*64*132 + 128*68 + 128*132)*4)   // 169984

#if defined(__CUDA_ARCH__) && (defined(__CUDA_ARCH_FEAT_SM103_ALL) || defined(__CUDA_ARCH_FEAT_SM100_ALL) || defined(__CUDA_ARCH_FEAT_SM101_ALL))
#define HAS_TCGEN05 1
#else
#define HAS_TCGEN05 0
#endif

typedef __half f16;

// ---------------- scratch globals -------------------------------------------
__device__ float g_x[Mrows*Dm];
__device__ __align__(256) f16 g_x0[Mrows*Dm], g_x1[Mrows*Dm];
__device__ float g_q[Mrows*Dm];
__device__ float g_k[Mrows*Dm];
__device__ float g_v[Mrows*Dm];
__device__ __align__(256) f16 g_a0[Mrows*Dm], g_a1[Mrows*Dm];
__device__ float g_o[Mrows*Dm];
__device__ __align__(256) f16 g_h0[(size_t)Mrows*Ff], g_h1[(size_t)Mrows*Ff];
__device__ float g_cos[Tseq*32];
__device__ float g_sin[Tseq*32];
__device__ float g_cnorm[Kcb];
__device__ int   g_idx[Mrows];
__device__ float g_lpart[Mrows];
__device__ float g_pb[Mrows*32];
__device__ int   g_pi[Mrows*32];
// split weights (transposed to [N][K]) and codebook, 2 fp16 planes each
__device__ __align__(256) f16 g_wq0[Lnum*DD], g_wq1[Lnum*DD];
__device__ __align__(256) f16 g_wk0[Lnum*DD], g_wk1[Lnum*DD];
__device__ __align__(256) f16 g_wv0[Lnum*DD], g_wv1[Lnum*DD];
__device__ __align__(256) f16 g_wo0[Lnum*DD], g_wo1[Lnum*DD];
__device__ __align__(256) f16 g_w10[(size_t)Lnum*Dm*Ff], g_w11[(size_t)Lnum*Dm*Ff];
__device__ __align__(256) f16 g_w20[(size_t)Lnum*Dm*Ff], g_w21[(size_t)Lnum*Dm*Ff];
__device__ __align__(256) f16 g_cb0[Kcb*Dm], g_cb1[Kcb*Dm];

// ---------------- helpers ----------------------------------------------------
__device__ __forceinline__ void split2(float v, f16& h, f16& l) {
    h = __float2half_rn(v);
    float r = v - __half2float(h);
    l = __float2half_rn(r);
}
__device__ __forceinline__ void st_f162(f16* p, f16 a, f16 b) {
    __half2 t; t.x = a; t.y = b;
    *reinterpret_cast<__half2*>(p) = t;
}
__device__ __forceinline__ void split2_store4(float4 v, f16* a0, f16* a1, size_t o) {
    f16 h[4], l[4];
    split2(v.x, h[0], l[0]); split2(v.y, h[1], l[1]);
    split2(v.z, h[2], l[2]); split2(v.w, h[3], l[3]);
    st_f162(a0 + o, h[0], h[1]); st_f162(a0 + o + 2, h[2], h[3]);
    st_f162(a1 + o, l[0], l[1]); st_f162(a1 + o + 2, l[2], l[3]);
}
__device__ __forceinline__ uint32_t smem_u32(const void* p) {
    return (uint32_t)__cvta_generic_to_shared(p);
}
__device__ __forceinline__ uint32_t elect_one() {
    uint32_t pred;
    asm volatile("{\n\t.reg .pred p;\n\telect.sync _|p, 0xFFFFFFFF;\n\tselp.b32 %0, 1, 0, p;\n\t}"
                 : "=r"(pred));
    return pred;
}
__device__ __forceinline__ void mwait(uint32_t a, uint32_t p) {
    asm volatile("{\n\t.reg .pred P;\n\tWL_%=:\n\t"
                 "mbarrier.try_wait.parity.acquire.cta.shared::cta.b64 P, [%0], %1, 0x989680;\n\t"
                 "@P bra WD_%=;\n\tbra WL_%=;\n\tWD_%=:\n\t}" :: "r"(a), "r"(p) : "memory");
}
#if HAS_TCGEN05
__device__ __forceinline__ void mma_f16_ss(uint32_t d, uint64_t a, uint64_t b, uint32_t en) {
    asm volatile("{\n\t.reg .pred p;\n\tsetp.ne.u32 p, %4, 0;\n\t"
                 "tcgen05.mma.cta_group::1.kind::f16 [%0], %1, %2, %3, {%5, %5, %5, %5}, p;\n\t}"
                 :: "r"(d), "l"(a), "l"(b), "r"(IDESC_FP16), "r"(en), "r"(0u) : "memory");
}
#define LDTM_X32(r, addr) \
    asm volatile("tcgen05.ld.sync.aligned.32x32b.x32.b32 " \
        "{%0,%1,%2,%3,%4,%5,%6,%7,%8,%9,%10,%11,%12,%13,%14,%15," \
        "%16,%17,%18,%19,%20,%21,%22,%23,%24,%25,%26,%27,%28,%29,%30,%31}, [%32];" \
        : "=r"((r)[0]),"=r"((r)[1]),"=r"((r)[2]),"=r"((r)[3]),"=r"((r)[4]),"=r"((r)[5]),"=r"((r)[6]),"=r"((r)[7]), \
          "=r"((r)[8]),"=r"((r)[9]),"=r"((r)[10]),"=r"((r)[11]),"=r"((r)[12]),"=r"((r)[13]),"=r"((r)[14]),"=r"((r)[15]), \
          "=r"((r)[16]),"=r"((r)[17]),"=r"((r)[18]),"=r"((r)[19]),"=r"((r)[20]),"=r"((r)[21]),"=r"((r)[22]),"=r"((r)[23]), \
          "=r"((r)[24]),"=r"((r)[25]),"=r"((r)[26]),"=r"((r)[27]),"=r"((r)[28]),"=r"((r)[29]),"=r"((r)[30]),"=r"((r)[31]) \
        : "r"(addr))
#endif

__device__ __forceinline__ float blockReduceSum(float v, float* sh) {
#pragma unroll
    for (int off = 16; off > 0; off >>= 1) v += __shfl_xor_sync(0xffffffffu, v, off);
    int warp = threadIdx.x >> 5, lane = threadIdx.x & 31;
    if (lane == 0) sh[warp] = v;
    __syncthreads();
    if (threadIdx.x == 0) {
        float s = 0.f; int nw = blockDim.x >> 5;
        for (int i = 0; i < nw; i++) s += sh[i];
        sh[0] = s;
    }
    __syncthreads();
    float r = sh[0];
    __syncthreads();
    return r;
}
__device__ __forceinline__ float gelu_exact(float v) {
    return 0.5f * v * (1.0f + erff(v * 0.70710678118654752f));
}

// ---------------- GEMM: C = A @ B^T (A,B = 2-plane fp16 splits) --------------
#if HAS_TCGEN05
__device__ __forceinline__ void ldtile(char* dst, const f16* src, int Kd, int r0, int k0, int tid) {
#pragma unroll
    for (int j = 0; j < 4; j++) {
        int s = tid + j * 256;             // 0..1023
        int r = s >> 3, cb = s & 7;
        uint32_t off = (uint32_t)((r << 7) | (cb << 4));
        off ^= (off >> 3) & 0x70;
        *(uint4*)(dst + off) = *(const uint4*)(src + (size_t)(r0 + r) * Kd + k0 + cb * 8);
    }
}
__device__ __forceinline__ void load_stage(char* st, const f16* A0, const f16* A1,
                                           const f16* B0, const f16* B1,
                                           int Kd, int row0, int col0, int k0, int tid) {
    ldtile(st,              A0, Kd, row0, k0, tid);
    ldtile(st + TILE_B,     A1, Kd, row0, k0, tid);
    ldtile(st + 2 * TILE_B, B0, Kd, col0,       k0, tid);
    ldtile(st + 3 * TILE_B, B0, Kd, col0 + 128, k0, tid);
    ldtile(st + 4 * TILE_B, B1, Kd, col0,       k0, tid);
    ldtile(st + 5 * TILE_B, B1, Kd, col0 + 128, k0, tid);
}
#endif

__global__ void __launch_bounds__(256, 1) __cluster_dims__(1, 1, 1)
gemm_tc(const f16* __restrict__ A0, const f16* __restrict__ A1,
        const f16* __restrict__ B0, const f16* __restrict__ B1,
        const float* __restrict__ bias,
        float* __restrict__ outf, int* __restrict__ outi,
        f16* __restrict__ o0, f16* __restrict__ o1,
        int Kd, int Ntot, int act) {
    extern __shared__ char sm[];
    int tid = threadIdx.x, wid = tid >> 5, lane = tid & 31;
    int row0 = blockIdx.y * BM, col0 = blockIdx.x * BN;
#if HAS_TCGEN05
    uint32_t sbase = smem_u32(sm);
    if (wid == 0) {
        asm volatile("tcgen05.alloc.cta_group::1.sync.aligned.shared::cta.b32 [%0], %1;"
                     :: "r"(sbase), "r"(256u) : "memory");
    }
    if (tid == 0) {
        asm volatile("mbarrier.init.shared.b64 [%0], %1;" :: "r"(sbase + 8), "r"(1u) : "memory");
        asm volatile("mbarrier.init.shared.b64 [%0], %1;" :: "r"(sbase + 16), "r"(1u) : "memory");
    }
    __syncthreads();
    uint32_t dt;
    asm volatile("ld.shared.b32 %0, [%1];" : "=r"(dt) : "r"(sbase));

    uint32_t s0off = ((sbase + 1024 + 1023) & ~1023u) - sbase;
    char* st0 = sm + s0off;
    char* st1 = st0 + STAGE_BYTES;
    uint32_t stb0 = sbase + s0off;
    const int NK = Kd >> 6;

    load_stage(st0, A0, A1, B0, B1, Kd, row0, col0, 0, tid);
    __syncthreads();
    uint32_t ph0 = 0, ph1 = 0;

    for (int k = 0; k < NK; k++) {
        uint32_t stb = stb0 + (uint32_t)(k & 1) * STAGE_BYTES;
        if (wid == 0) {
            asm volatile("fence.proxy.async.shared::cta;" ::: "memory");
            if (elect_one()) {
                uint64_t da0 = DESC_BASE | ((uint64_t)(stb >> 4) & 0x3FFF);
                uint64_t da1 = DESC_BASE | ((uint64_t)((stb + TILE_B) >> 4) & 0x3FFF);
#pragma unroll
                for (int nb = 0; nb < 4; nb++) {       // four N=64 column blocks
                    uint32_t d = dt + nb * 64;
                    uint32_t sub = (uint32_t)(nb >> 1) * TILE_B;  // 128-row sub-tile
                    uint64_t db0 = DESC_BASE | ((uint64_t)((stb + 2 * TILE_B + sub) >> 4) & 0x3FFF);
                    uint64_t db1 = DESC_BASE | ((uint64_t)((stb + 4 * TILE_B + sub) >> 4) & 0x3FFF);
                    uint64_t bo = (uint64_t)((nb & 1) * 512);     // 64 rows * 128B in 16B units
#pragma unroll
                    for (int kk = 0; kk < 4; kk++) {   // K=16 per MMA
                        uint64_t ao = (uint64_t)(kk * 2);
                        uint64_t bk = bo + kk * 2;
                        uint32_t en = (k > 0) || (kk > 0);
                        mma_f16_ss(d, da0 + ao, db0 + bk, en);   // hh
                        mma_f16_ss(d, da0 + ao, db1 + bk, 1u);   // hl
                        mma_f16_ss(d, da1 + ao, db0 + bk, 1u);   // lh
                    }
                }
                asm volatile("tcgen05.commit.cta_group::1.mbarrier::arrive::one.shared::cluster.b64 [%0];"
                             :: "r"(sbase + 8 + (uint32_t)(k & 1) * 8) : "memory");
            }
        }
        if (k + 1 < NK) {
            if (k >= 1) {
                if (((k + 1) & 1) == 0) { mwait(sbase + 8, ph0); ph0 ^= 1; }
                else                    { mwait(sbase + 16, ph1); ph1 ^= 1; }
            }
            load_stage((k & 1) ? st0 : st1, A0, A1, B0, B1, Kd, row0, col0, (k + 1) << 6, tid);
        }
        __syncthreads();
    }
    if (((NK - 1) & 1) == 0) { mwait(sbase + 8, ph0); }
    else                     { mwait(sbase + 16, ph1); }
    asm volatile("tcgen05.fence::after_thread_sync;" ::: "memory");

    if (wid < 4) {
        int row = row0 + wid * 32 + lane;
        if (act == 2) {
            float best = 3.4e38f; int bi = 0;
            for (int c0 = 0; c0 < 8; c0++) {
                uint32_t r[32];
                LDTM_X32(r, dt + c0 * 32);
                asm volatile("tcgen05.wait::ld.sync.aligned;" ::: "memory");
#pragma unroll
                for (int j = 0; j < 32; j++) {
                    int code = col0 + c0 * 32 + j;
                    float d = __ldg(bias + code) - 2.0f * __uint_as_float(r[j]);
                    if (d < best) { best = d; bi = code; }
                }
            }
            outf[(size_t)row * gridDim.x + blockIdx.x] = best;
            outi[(size_t)row * gridDim.x + blockIdx.x] = bi;
        } else if (act == 1) {
            for (int c0 = 0; c0 < 8; c0++) {
                uint32_t r[32];
                LDTM_X32(r, dt + c0 * 32);
                asm volatile("tcgen05.wait::ld.sync.aligned;" ::: "memory");
                size_t base = (size_t)row * Ntot + col0 + c0 * 32;
#pragma unroll
                for (int j2 = 0; j2 < 16; j2++) {
                    int c = c0 * 32 + j2 * 2;
                    float v0 = gelu_exact(__uint_as_float(r[j2 * 2])     + __ldg(bias + col0 + c));
                    float v1 = gelu_exact(__uint_as_float(r[j2 * 2 + 1]) + __ldg(bias + col0 + c + 1));
                    f16 h0, l0, h1, l1;
                    split2(v0, h0, l0); split2(v1, h1, l1);
                    st_f162(o0 + base + j2 * 2, h0, h1);
                    st_f162(o1 + base + j2 * 2, l0, l1);
                }
            }
        } else {
            for (int c0 = 0; c0 < 8; c0++) {
                uint32_t r[32];
                LDTM_X32(r, dt + c0 * 32);
                asm volatile("tcgen05.wait::ld.sync.aligned;" ::: "memory");
                size_t base = (size_t)row * Ntot + col0 + c0 * 32;
#pragma unroll
                for (int j4 = 0; j4 < 8; j4++) {
                    float4 ov; float* op = &ov.x;
#pragma unroll
                    for (int j = 0; j < 4; j++)
                        op[j] = __uint_as_float(r[j4 * 4 + j]) + __ldg(bias + col0 + c0 * 32 + j4 * 4 + j);
                    *(float4*)(outf + base + j4 * 4) = ov;
                }
            }
        }
    }
    __syncthreads();
    if (tid == 0) {
        asm volatile("mbarrier.inval.shared.b64 [%0];" :: "r"(sbase + 8) : "memory");
        asm volatile("mbarrier.inval.shared.b64 [%0];" :: "r"(sbase + 16) : "memory");
    }
    if (wid == 0) {
        asm volatile("tcgen05.relinquish_alloc_permit.cta_group::1.sync.aligned;");
        asm volatile("tcgen05.dealloc.cta_group::1.sync.aligned.b32 %0, %1;" :: "r"(dt), "r"(256u));
    }
#else
    // ---------- portable fp32 FFMA fallback (identical semantics) ----------
    const int W = 132;
    float* As = (float*)sm;
    float* Bs = As + 16 * W;
    int tx = tid & 15, ty = tid >> 4;
    float runb[8]; int runi[8];
#pragma unroll
    for (int i = 0; i < 8; i++) { runb[i] = 3.4e38f; runi[i] = 0; }
    float carry = 3.4e38f; int carryi = 0;
    for (int nh = 0; nh < 2; nh++) {
        int ch0 = col0 + nh * 128;
        float acc[8][8] = {};
        for (int k0 = 0; k0 < Kd; k0 += 16) {
            __syncthreads();
#pragma unroll
            for (int j = 0; j < 8; j++) {
                int s = tid + j * 256; int m = s & 127, kk = s >> 7;
                size_t ga = (size_t)(row0 + m) * Kd + k0 + kk;
                As[kk * W + m] = __half2float(A0[ga]) + __half2float(A1[ga]);
                size_t gb = (size_t)(ch0 + m) * Kd + k0 + kk;
                Bs[kk * W + m] = __half2float(B0[gb]) + __half2float(B1[gb]);
            }
            __syncthreads();
#pragma unroll
            for (int kk = 0; kk < 16; kk++) {
                float a[8], b[8];
#pragma unroll
                for (int i = 0; i < 8; i++) a[i] = As[kk * W + ty * 8 + i];
#pragma unroll
                for (int j = 0; j < 8; j++) b[j] = Bs[kk * W + tx * 8 + j];
#pragma unroll
                for (int i = 0; i < 8; i++)
#pragma unroll
                    for (int j = 0; j < 8; j++) acc[i][j] += a[i] * b[j];
            }
        }
        if (act == 2) {
#pragma unroll
            for (int i = 0; i < 8; i++)
#pragma unroll
                for (int j = 0; j < 8; j++) {
                    int code = ch0 + tx * 8 + j;
                    float d = __ldg(bias + code) - 2.0f * acc[i][j];
                    if (d < runb[i]) { runb[i] = d; runi[i] = code; }
                }
            __syncthreads();
            float* bvs = (float*)sm;
            int*   bis = (int*)(sm + 8192);
#pragma unroll
            for (int i = 0; i < 8; i++) { bvs[(ty * 8 + i) * 16 + tx] = runb[i]; bis[(ty * 8 + i) * 16 + tx] = runi[i]; }
            __syncthreads();
            if (tid < 128) {
                float bb = bvs[tid * 16]; int bi = bis[tid * 16];
                for (int t2 = 1; t2 < 16; t2++) {
                    float v = bvs[tid * 16 + t2]; int c = bis[tid * 16 + t2];
                    if (v < bb || (v == bb && c < bi)) { bb = v; bi = c; }
                }
                if (bb < carry) { carry = bb; carryi = bi; }
            }
            __syncthreads();
        } else if (act == 1) {
#pragma unroll
            for (int i = 0; i < 8; i++) {
                size_t base = (size_t)(row0 + ty * 8 + i) * Ntot + ch0 + tx * 8;
#pragma unroll
                for (int j = 0; j < 8; j++) {
                    float v = gelu_exact(acc[i][j] + __ldg(bias + ch0 + tx * 8 + j));
                    f16 h, l; split2(v, h, l);
                    o0[base + j] = h; o1[base + j] = l;
                }
            }
        } else {
#pragma unroll
            for (int i = 0; i < 8; i++) {
                size_t base = (size_t)(row0 + ty * 8 + i) * Ntot + ch0 + tx * 8;
#pragma unroll
                for (int j = 0; j < 8; j++)
                    outf[base + j] = acc[i][j] + __ldg(bias + ch0 + tx * 8 + j);
            }
        }
    }
    if (act == 2 && tid < 128) {
        outf[(size_t)(row0 + tid) * gridDim.x + blockIdx.x] = carry;
        outi[(size_t)(row0 + tid) * gridDim.x + blockIdx.x] = carryi;
    }
#endif
}

// ---------------- weight split+transpose ([K][N] -> 2x fp16 [N][K]) ----------
__global__ void tsplit(const float* __restrict__ Wm, f16* __restrict__ O0,
                       f16* __restrict__ O1, int Kd, int Nd) {
    __shared__ float t[32][33];
    int n0 = blockIdx.x << 5, k0 = blockIdx.y << 5;
    int tx = threadIdx.x, ty = threadIdx.y;  // (32,8)
#pragma unroll
    for (int i = 0; i < 4; i++) {
        int k = ty + i * 8;
        t[k][tx] = Wm[(size_t)(k0 + k) * Nd + n0 + tx];
    }
    __syncthreads();
#pragma unroll
    for (int i = 0; i < 4; i++) {
        int n = ty + i * 8;
        f16 h, l; split2(t[tx][n], h, l);
        size_t o = (size_t)(n0 + n) * Kd + k0 + tx;
        O0[o] = h; O1[o] = l;
    }
}

__global__ void esplit(const float* __restrict__ X, f16* __restrict__ O0,
                       f16* __restrict__ O1, int n) {
    int i = blockIdx.x * blockDim.x + threadIdx.x;
    if (i >= n) return;
    f16 h, l; split2(X[i], h, l);
    O0[i] = h; O1[i] = l;
}

// ---------------- embedding gather (+split) ----------------------------------
__global__ void embed_kernel(const int* __restrict__ ids, const float* __restrict__ emb) {
    int i = blockIdx.x * blockDim.x + threadIdx.x;
    if (i >= Mrows * 128) return;
    int row = i >> 7, c4 = (i & 127) << 2;
    float4 v = *(const float4*)(emb + (size_t)ids[row] * Dm + c4);
    size_t o = (size_t)row * Dm + c4;
    *(float4*)(g_x + o) = v;
    split2_store4(v, g_x0, g_x1, o);
}

// ---------------- RoPE --------------------------------------------------------
__global__ void rope_tables() {
    int i = blockIdx.x * blockDim.x + threadIdx.x;
    if (i >= Tseq * 32) return;
    int t = i >> 5, j = i & 31;
    float invf = 1.0f / powf(10000.0f, (2.0f * (float)j) / 64.0f);
    float ang = (float)t * invf;
    g_cos[i] = cosf(ang); g_sin[i] = sinf(ang);
}

__global__ void rope_apply() {
    int i = blockIdx.x * blockDim.x + threadIdx.x;
    if (i >= Mrows * Hn * 32) return;
    int j = i & 31, h = (i >> 5) & 7, bt = i >> 8, t = bt & (Tseq - 1);
    float c = g_cos[(t << 5) + j], s = g_sin[(t << 5) + j];
    size_t base = ((size_t)bt * Hn + h) * HDim;
    float q1 = g_q[base + j], q2 = g_q[base + j + 32];
    g_q[base + j] = q1 * c - q2 * s; g_q[base + j + 32] = q2 * c + q1 * s;
    float k1 = g_k[base + j], k2 = g_k[base + j + 32];
    g_k[base + j] = k1 * c - k2 * s; g_k[base + j + 32] = k2 * c + k1 * s;
}

// ---------------- attention (fp32 flash, 128q x 128k tiles, 8x8 microtile) ----
__global__ void __launch_bounds__(256, 1)
attention_kernel() {
    extern __shared__ float as_[];
    float* Qts = as_;                         // [64][132] (d, q)
    float* Kts = as_ + 64 * 132;              // [64][132] (d, k)
    float* Vs  = as_ + 2 * 64 * 132;          // [128][68] (k, d)
    float* Ps  = as_ + 2 * 64 * 132 + 128 * 68;  // [128][132] (q, k)
    int qt = blockIdx.x, h = blockIdx.y, b = blockIdx.z;
    int tid = threadIdx.x, tx = tid & 15, ty = tid >> 4;
    int t0 = qt * 128;
    // load Q^T (128 rows x 64 d)
    for (int it = tid; it < 2048; it += 256) {
        int r = it >> 4, d4 = (it & 15) << 2;
        float4 v = *(const float4*)(g_q + (size_t)(b * Tseq + t0 + r) * Dm + h * HDim + d4);
        Qts[(d4 + 0) * 132 + r] = v.x; Qts[(d4 + 1) * 132 + r] = v.y;
        Qts[(d4 + 2) * 132 + r] = v.z; Qts[(d4 + 3) * 132 + r] = v.w;
    }
    float m[8], l[8], o[8][4];
#pragma unroll
    for (int i = 0; i < 8; i++) {
        m[i] = -1e30f; l[i] = 0.f;
#pragma unroll
        for (int j = 0; j < 4; j++) o[i][j] = 0.f;
    }
    for (int kt = 0; kt < 4; kt++) {
        __syncthreads();   // prev PV (reads Ps, Vs) done; Q load done at kt=0
        int k0 = kt * 128;
        for (int it = tid; it < 2048; it += 256) {
            int r = it >> 4, d4 = (it & 15) << 2;
            size_t gb = (size_t)(b * Tseq + k0 + r) * Dm + h * HDim + d4;
            float4 kv = *(const float4*)(g_k + gb);
            Kts[(d4 + 0) * 132 + r] = kv.x; Kts[(d4 + 1) * 132 + r] = kv.y;
            Kts[(d4 + 2) * 132 + r] = kv.z; Kts[(d4 + 3) * 132 + r] = kv.w;
            *(float4*)&Vs[r * 68 + d4] = *(const float4*)(g_v + gb);
        }
        __syncthreads();
        float s[8][8] = {};
        for (int d = 0; d < 64; d++) {
            float a[8], bb[8];
            *(float4*)&a[0]  = *(float4*)&Qts[d * 132 + ty * 8];
            *(float4*)&a[4]  = *(float4*)&Qts[d * 132 + ty * 8 + 4];
            *(float4*)&bb[0] = *(float4*)&Kts[d * 132 + tx * 8];
            *(float4*)&bb[4] = *(float4*)&Kts[d * 132 + tx * 8 + 4];
#pragma unroll
            for (int i = 0; i < 8; i++)
#pragma unroll
                for (int j = 0; j < 8; j++) s[i][j] += a[i] * bb[j];
        }
#pragma unroll
        for (int i = 0; i < 8; i++) {
#pragma unroll
            for (int j = 0; j < 8; j++) s[i][j] *= 0.125f;
            float rm = s[i][0];
#pragma unroll
            for (int j = 1; j < 8; j++) rm = fmaxf(rm, s[i][j]);
#pragma unroll
            for (int off = 8; off > 0; off >>= 1) rm = fmaxf(rm, __shfl_xor_sync(0xffffffffu, rm, off));
            float mn = fmaxf(m[i], rm);
            float corr = expf(m[i] - mn);
            float rs = 0.f;
#pragma unroll
            for (int j = 0; j < 8; j++) { s[i][j] = expf(s[i][j] - mn); rs += s[i][j]; }
#pragma unroll
            for (int off = 8; off > 0; off >>= 1) rs += __shfl_xor_sync(0xffffffffu, rs, off);
            l[i] = l[i] * corr + rs;
#pragma unroll
            for (int j = 0; j < 4; j++) o[i][j] *= corr;
            m[i] = mn;
            *(float4*)&Ps[(ty * 8 + i) * 132 + tx * 8]     = make_float4(s[i][0], s[i][1], s[i][2], s[i][3]);
            *(float4*)&Ps[(ty * 8 + i) * 132 + tx * 8 + 4] = make_float4(s[i][4], s[i][5], s[i][6], s[i][7]);
        }
        __syncthreads();   // P complete before PV reads
        for (int k2 = 0; k2 < 128; k2++) {
            float4 bv = *(float4*)&Vs[k2 * 68 + tx * 4];
#pragma unroll
            for (int i = 0; i < 8; i++) {
                float a = Ps[(ty * 8 + i) * 132 + k2];
                o[i][0] += a * bv.x; o[i][1] += a * bv.y;
                o[i][2] += a * bv.z; o[i][3] += a * bv.w;
            }
        }
    }
#pragma unroll
    for (int i = 0; i < 8; i++) {
        float inv = 1.0f / l[i];
        float4 ov = make_float4(o[i][0] * inv, o[i][1] * inv, o[i][2] * inv, o[i][3] * inv);
        size_t ob = (size_t)(b * Tseq + t0 + ty * 8 + i) * Dm + h * HDim + tx * 4;
        split2_store4(ov, g_a0, g_a1, ob);
    }
}

// ---------------- residual add + LayerNorm (writes x + split2) ----------------
__global__ void add_ln(float* __restrict__ x, const float* __restrict__ r,
                       const float* __restrict__ g, const float* __restrict__ b) {
    __shared__ float sh[8];
    int row = blockIdx.x, tid = threadIdx.x;
    size_t base = (size_t)row * Dm + (tid << 2);
    float4 xv = *(float4*)(x + base);
    float4 rv = *(const float4*)(r + base);
    float v0 = xv.x + rv.x, v1 = xv.y + rv.y, v2 = xv.z + rv.z, v3 = xv.w + rv.w;
    float mean = blockReduceSum(v0 + v1 + v2 + v3, sh) * (1.0f / Dm);
    float d0 = v0 - mean, d1 = v1 - mean, d2 = v2 - mean, d3 = v3 - mean;
    float var = blockReduceSum(d0 * d0 + d1 * d1 + d2 * d2 + d3 * d3, sh) * (1.0f / Dm);
    float inv = rsqrtf(var + 1e-5f);
    int c = tid << 2;
    float4 ov;
    ov.x = d0 * inv * g[c] + b[c];         ov.y = d1 * inv * g[c + 1] + b[c + 1];
    ov.z = d2 * inv * g[c + 2] + b[c + 2]; ov.w = d3 * inv * g[c + 3] + b[c + 3];
    *(float4*)(x + base) = ov;
    split2_store4(ov, g_x0, g_x1, base);
}

// ---------------- VQ helpers ---------------------------------------------------
__global__ void cnorm_kernel(const float* __restrict__ cbp) {
    __shared__ float sh[8];
    int code = blockIdx.x, tid = threadIdx.x;
    float4 v = *(const float4*)(cbp + (size_t)code * Dm + (tid << 2));
    float s = blockReduceSum(v.x * v.x + v.y * v.y + v.z * v.z + v.w * v.w, sh);
    if (tid == 0) g_cnorm[code] = s;
}

__global__ void vq_reduce() {
    int row = blockIdx.x * blockDim.x + threadIdx.x;
    if (row >= Mrows) return;
    float b = g_pb[(size_t)row * 32]; int bi = g_pi[(size_t)row * 32];
    for (int t = 1; t < 32; t++) {
        float v = g_pb[(size_t)row * 32 + t];
        int   c = g_pi[(size_t)row * 32 + t];
        if (v < b || (v == b && c < bi)) { b = v; bi = c; }
    }
    g_idx[row] = bi;
}

__global__ void vq_out(const float* __restrict__ cbp, float* __restrict__ out, int writeIdx) {
    __shared__ float sh[8];
    int row = blockIdx.x, tid = threadIdx.x;
    int id = g_idx[row];
    size_t zb = (size_t)row * Dm + (tid << 2);
    float4 z = *(const float4*)(g_x + zb);
    float4 c = *(const float4*)(cbp + (size_t)id * Dm + (tid << 2));
    float4 q;
    q.x = z.x + (c.x - z.x); q.y = z.y + (c.y - z.y);
    q.z = z.z + (c.z - z.z); q.w = z.w + (c.w - z.w);
    *(float4*)(out + zb) = q;
    float dx = z.x - c.x, dy = z.y - c.y, dz = z.z - c.z, dw = z.w - c.w;
    float s = blockReduceSum(dx * dx + dy * dy + dz * dz + dw * dw, sh);
    if (tid == 0) {
        g_lpart[row] = s;
        if (writeIdx) out[(size_t)Mrows * Dm + row] = (float)id;
    }
}

__global__ void loss_final(float* __restrict__ out, int writeLoss, size_t off) {
    __shared__ float sh[8];
    int tid = threadIdx.x;
    float s = 0.f;
    for (int i = tid; i < Mrows; i += 256) s += g_lpart[i];
    s = blockReduceSum(s, sh);
    if (tid == 0 && writeLoss) out[off] = 0.3f * s / (float)((size_t)Mrows * Dm);
}

// ---------------- host orchestration ------------------------------------------
extern "C" void kernel_launch(void* const* d_in, const int* in_sizes, int n_in,
                              void* d_out, int out_size) {
    const int*   ids  = (const int*)  d_in[0];
    const float* emb  = (const float*)d_in[1];
    const float* Wq   = (const float*)d_in[2];
    const float* bq   = (const float*)d_in[3];
    const float* Wk   = (const float*)d_in[4];
    const float* bk   = (const float*)d_in[5];
    const float* Wv   = (const float*)d_in[6];
    const float* bv   = (const float*)d_in[7];
    const float* Wo   = (const float*)d_in[8];
    const float* bo   = (const float*)d_in[9];
    const float* ln1g = (const float*)d_in[10];
    const float* ln1b = (const float*)d_in[11];
    const float* W1   = (const float*)d_in[12];
    const float* b1   = (const float*)d_in[13];
    const float* W2   = (const float*)d_in[14];
    const float* b2   = (const float*)d_in[15];
    const float* ln2g = (const float*)d_in[16];
    const float* ln2b = (const float*)d_in[17];
    const float* cb   = (const float*)d_in[18];
    float* out = (float*)d_out;

    cudaFuncSetAttribute(gemm_tc, cudaFuncAttributeMaxDynamicSharedMemorySize, SMEM_DYN);
    cudaFuncSetAttribute(attention_kernel, cudaFuncAttributeMaxDynamicSharedMemorySize, ATT_SMEM);

    float *px, *pq, *pk, *pv, *po, *pcn, *ppb;
    int *ppi;
    f16 *x0, *x1, *a0, *a1, *h0, *h1;
    f16 *wq0, *wq1, *wk0, *wk1, *wv0, *wv1, *wo0, *wo1;
    f16 *w10, *w11, *w20, *w21, *cb0, *cb1;
    cudaGetSymbolAddress((void**)&px, g_x);
    cudaGetSymbolAddress((void**)&pq, g_q);   cudaGetSymbolAddress((void**)&pk, g_k);
    cudaGetSymbolAddress((void**)&pv, g_v);   cudaGetSymbolAddress((void**)&po, g_o);
    cudaGetSymbolAddress((void**)&pcn, g_cnorm);
    cudaGetSymbolAddress((void**)&ppb, g_pb); cudaGetSymbolAddress((void**)&ppi, g_pi);
    cudaGetSymbolAddress((void**)&x0, g_x0);  cudaGetSymbolAddress((void**)&x1, g_x1);
    cudaGetSymbolAddress((void**)&a0, g_a0);  cudaGetSymbolAddress((void**)&a1, g_a1);
    cudaGetSymbolAddress((void**)&h0, g_h0);  cudaGetSymbolAddress((void**)&h1, g_h1);
    cudaGetSymbolAddress((void**)&wq0, g_wq0); cudaGetSymbolAddress((void**)&wq1, g_wq1);
    cudaGetSymbolAddress((void**)&wk0, g_wk0); cudaGetSymbolAddress((void**)&wk1, g_wk1);
    cudaGetSymbolAddress((void**)&wv0, g_wv0); cudaGetSymbolAddress((void**)&wv1, g_wv1);
    cudaGetSymbolAddress((void**)&wo0, g_wo0); cudaGetSymbolAddress((void**)&wo1, g_wo1);
    cudaGetSymbolAddress((void**)&w10, g_w10); cudaGetSymbolAddress((void**)&w11, g_w11);
    cudaGetSymbolAddress((void**)&w20, g_w20); cudaGetSymbolAddress((void**)&w21, g_w21);
    cudaGetSymbolAddress((void**)&cb0, g_cb0); cudaGetSymbolAddress((void**)&cb1, g_cb1);

    dim3 tb(32, 8);
    dim3 gDD(Dm / BN, Mrows / BM);    // (2,128)
    dim3 gDF(Ff / BN, Mrows / BM);    // (8,128)
    dim3 gVQ(Kcb / BN, Mrows / BM);   // (32,128)

    // ---- prologue, ordered so launch #6 (index 5) is gemm_tc (ncu -s 5 -c 1) --
    embed_kernel<<<(Mrows * 128 + 255) / 256, 256>>>(ids, emb);                 // 1
    tsplit<<<dim3(Dm / 32, Dm / 32), tb>>>(Wq, wq0, wq1, Dm, Dm);               // 2 (layer 0)
    tsplit<<<dim3(Dm / 32, Dm / 32), tb>>>(Wk, wk0, wk1, Dm, Dm);               // 3
    tsplit<<<dim3(Dm / 32, Dm / 32), tb>>>(Wv, wv0, wv1, Dm, Dm);               // 4
    tsplit<<<dim3(Dm / 32, Dm / 32), tb>>>(Wo, wo0, wo1, Dm, Dm);               // 5
    gemm_tc<<<gDD, 256, SMEM_DYN>>>(x0, x1, wq0, wq1, bq, pq, 0, 0, 0,          // 6 <- profiled
                                    Dm, Dm, 0);
    // remaining prologue
    for (int l = 0; l < Lnum; l++) {
        size_t wo_off = (size_t)l * DD, f_off = (size_t)l * Dm * Ff;
        if (l > 0) {
            tsplit<<<dim3(Dm / 32, Dm / 32), tb>>>(Wq + wo_off, wq0 + wo_off, wq1 + wo_off, Dm, Dm);
            tsplit<<<dim3(Dm / 32, Dm / 32), tb>>>(Wk + wo_off, wk0 + wo_off, wk1 + wo_off, Dm, Dm);
            tsplit<<<dim3(Dm / 32, Dm / 32), tb>>>(Wv + wo_off, wv0 + wo_off, wv1 + wo_off, Dm, Dm);
            tsplit<<<dim3(Dm / 32, Dm / 32), tb>>>(Wo + wo_off, wo0 + wo_off, wo1 + wo_off, Dm, Dm);
        }
        tsplit<<<dim3(Ff / 32, Dm / 32), tb>>>(W1 + f_off, w10 + f_off, w11 + f_off, Dm, Ff);
        tsplit<<<dim3(Dm / 32, Ff / 32), tb>>>(W2 + f_off, w20 + f_off, w21 + f_off, Ff, Dm);
    }
    esplit<<<(Kcb * Dm + 255) / 256, 256>>>(cb, cb0, cb1, Kcb * Dm);
    cnorm_kernel<<<Kcb, 128>>>(cb);
    rope_tables<<<(Tseq * 32 + 255) / 256, 256>>>();

    for (int l = 0; l < Lnum; l++) {
        size_t wo_off = (size_t)l * DD, f_off = (size_t)l * Dm * Ff;
        if (l > 0)
            gemm_tc<<<gDD, 256, SMEM_DYN>>>(x0, x1, wq0 + wo_off, wq1 + wo_off,
                                            bq + l * Dm, pq, 0, 0, 0, Dm, Dm, 0);
        gemm_tc<<<gDD, 256, SMEM_DYN>>>(x0, x1, wk0 + wo_off, wk1 + wo_off,
                                        bk + l * Dm, pk, 0, 0, 0, Dm, Dm, 0);
        gemm_tc<<<gDD, 256, SMEM_DYN>>>(x0, x1, wv0 + wo_off, wv1 + wo_off,
                                        bv + l * Dm, pv, 0, 0, 0, Dm, Dm, 0);
        rope_apply<<<(Mrows * Hn * 32 + 255) / 256, 256>>>();
        attention_kernel<<<dim3(Tseq / 128, Hn, Bsz), 256, ATT_SMEM>>>();
        gemm_tc<<<gDD, 256, SMEM_DYN>>>(a0, a1, wo0 + wo_off, wo1 + wo_off,
                                        bo + l * Dm, po, 0, 0, 0, Dm, Dm, 0);
        add_ln<<<Mrows, 128>>>(px, po, ln1g + l * Dm, ln1b + l * Dm);
        gemm_tc<<<gDF, 256, SMEM_DYN>>>(x0, x1, w10 + f_off, w11 + f_off,
                                        b1 + l * Ff, 0, 0, h0, h1, Dm, Ff, 1);
        gemm_tc<<<gDD, 256, SMEM_DYN>>>(h0, h1, w20 + f_off, w21 + f_off,
                                        b2 + l * Dm, po, 0, 0, 0, Ff, Dm, 0);
        add_ln<<<Mrows, 128>>>(px, po, ln2g + l * Dm, ln2b + l * Dm);
    }

    gemm_tc<<<gVQ, 256, SMEM_DYN>>>(x0, x1, cb0, cb1, pcn, ppb, ppi, 0, 0, Dm, Kcb, 2);
    vq_reduce<<<(Mrows + 255) / 256, 256>>>();

    size_t quantN = (size_t)Mrows * Dm;
    int writeIdx = (out_size >= (int)(quantN + Mrows)) ? 1 : 0;
    int writeLoss = 0;
    size_t lossOff = quantN + Mrows;
    if (out_size >= (int)(quantN + Mrows + 1)) { writeLoss = 1; lossOff = quantN + Mrows; }
    else if (out_size == (int)(quantN + 1))    { writeLoss = 1; lossOff = quantN; }

    vq_out<<<Mrows, 128>>>(cb, out, writeIdx);
    loss_final<<<1, 256>>>(out, writeLoss, lossOff);
}